// round 15
// baseline (speedup 1.0000x reference)
#include <cuda_runtime.h>
#include <cstdint>

// NodeDropout: out[e] = values[e] if neither endpoint is dropped, else 0.
// edge_index: int32 [2, E], values: f32 [E], nodes_flag: int32 [N]. Output: f32 [E].
//
// R15: single fused kernel. The flag->bitmask pack now runs inside the main
// kernel (consumer warps pack cooperatively grid-wide, ~1us, overlapped with
// the producer warp prefilling the bulk-load pipeline), followed by a global
// spin barrier (atomic arrive counter, reset by the last exiting CTA so graph
// replays are deterministic). Main pipeline identical to R14: 3-stage bulk
// loads of src/dst, values register-prefetched one tile ahead, consumer
// STG.128 output, 125 KB smem-resident bitmask. Eliminates the pack kernel
// launch + inter-kernel gap (R14: total-main = 6.1us).

static constexpr int MAX_WORDS = 32768;
__device__ unsigned int g_bits[MAX_WORDS];
__device__ int g_arrive;   // grid barrier arrive count (reset each launch)
__device__ int g_exit;     // exit count for reset handshake

static constexpr int NCONS_W     = 16;                    // consumer warps
static constexpr int CONS_T      = NCONS_W * 32;          // 512 consumer threads
static constexpr int THREADS     = CONS_T + 32;           // +1 producer warp = 544
static constexpr int GPG         = 2;                     // float4-groups per thread
static constexpr int GPT         = CONS_T * GPG;          // 1024 groups per tile
static constexpr int BUF_BYTES   = GPT * 16;              // 16384 per array per stage
static constexpr int STAGE_BYTES = 2 * BUF_BYTES;         // src + dst
static constexpr int NSTAGES     = 3;
static constexpr int MBAR_OFF    = 0;                     // full@16s, empty@16s+8
static constexpr int BUF_OFF     = 128;
static constexpr int BITS_OFF    = BUF_OFF + NSTAGES * STAGE_BYTES; // 98432

// ---- PTX helpers ----
__device__ __forceinline__ uint32_t smem_u32(const void* p) {
    return (uint32_t)__cvta_generic_to_shared(p);
}
__device__ __forceinline__ void mbar_init(uint32_t a, uint32_t cnt) {
    asm volatile("mbarrier.init.shared.b64 [%0], %1;" :: "r"(a), "r"(cnt) : "memory");
}
__device__ __forceinline__ void mbar_expect_tx(uint32_t a, uint32_t bytes) {
    asm volatile("mbarrier.arrive.expect_tx.shared.b64 _, [%0], %1;" :: "r"(a), "r"(bytes) : "memory");
}
__device__ __forceinline__ void mbar_arrive(uint32_t a) {
    asm volatile("mbarrier.arrive.shared.b64 _, [%0];" :: "r"(a) : "memory");
}
__device__ __forceinline__ void mbar_wait(uint32_t a, uint32_t parity) {
    uint32_t done = 0;
    while (!done) {
        asm volatile(
            "{\n\t.reg .pred p;\n\t"
            "mbarrier.try_wait.parity.shared.b64 p, [%1], %2;\n\t"
            "selp.b32 %0, 1, 0, p;\n\t}"
            : "=r"(done) : "r"(a), "r"(parity) : "memory");
    }
}
__device__ __forceinline__ void bulk_g2s(uint32_t dst, const void* src,
                                         uint32_t bytes, uint32_t mbar) {
    asm volatile(
        "cp.async.bulk.shared::cluster.global.mbarrier::complete_tx::bytes "
        "[%0], [%1], %2, [%3];"
        :: "r"(dst), "l"(src), "r"(bytes), "r"(mbar) : "memory");
}

__device__ __forceinline__ float4 mask_one(const unsigned int* s_bits,
                                           int4 s, int4 d, float4 v) {
    unsigned int b0 = (s_bits[((unsigned)s.x) >> 5] >> (s.x & 31)) |
                      (s_bits[((unsigned)d.x) >> 5] >> (d.x & 31));
    unsigned int b1 = (s_bits[((unsigned)s.y) >> 5] >> (s.y & 31)) |
                      (s_bits[((unsigned)d.y) >> 5] >> (d.y & 31));
    unsigned int b2 = (s_bits[((unsigned)s.z) >> 5] >> (s.z & 31)) |
                      (s_bits[((unsigned)d.z) >> 5] >> (d.z & 31));
    unsigned int b3 = (s_bits[((unsigned)s.w) >> 5] >> (s.w & 31)) |
                      (s_bits[((unsigned)d.w) >> 5] >> (d.w & 31));
    float4 o;
    o.x = (b0 & 1u) ? 0.0f : v.x;
    o.y = (b1 & 1u) ? 0.0f : v.y;
    o.z = (b2 & 1u) ? 0.0f : v.z;
    o.w = (b3 & 1u) ? 0.0f : v.w;
    return o;
}

// ---- Fused persistent kernel ----
__global__ __launch_bounds__(THREADS, 1)
void node_dropout_fused(const int4* __restrict__ src4,
                        const int4* __restrict__ dst4,
                        const float4* __restrict__ vals,
                        const int4* __restrict__ flag4,
                        float4* __restrict__ out,
                        int n4, int ntiles, int nwords,
                        int nflag4, int nwords4) {
    extern __shared__ __align__(16) unsigned char smem_raw[];
    unsigned int* s_bits = (unsigned int*)(smem_raw + BITS_OFF);
    uint32_t mb = smem_u32(smem_raw + MBAR_OFF);
    int tid  = threadIdx.x;
    int warp = tid >> 5;
    int lane = tid & 31;

    if (tid == 0) {
        for (int s = 0; s < NSTAGES; s++) {
            mbar_init(mb + 16 * s,     1);        // full (expect_tx)
            mbar_init(mb + 16 * s + 8, NCONS_W);  // empty
        }
    }
    __syncthreads();

    if (warp == NCONS_W) {
        // ---- Producer (lane 0): streams immediately; no bitmask dependency ----
        if (lane == 0) {
            int stage = 0, phase = 1;   // fresh barrier: parity-1 waits pass
            for (int t = blockIdx.x; t < ntiles; t += gridDim.x) {
                int g0 = t * GPT;
                uint32_t bytes = (uint32_t)min(GPT, n4 - g0) * 16u;
                uint32_t full = mb + 16 * stage;
                mbar_wait(full + 8, phase);       // empty
                mbar_expect_tx(full, bytes * 2u);
                uint32_t base = smem_u32(smem_raw + BUF_OFF + stage * STAGE_BYTES);
                bulk_g2s(base,             src4 + g0, bytes, full);
                bulk_g2s(base + BUF_BYTES, dst4 + g0, bytes, full);
                if (++stage == NSTAGES) { stage = 0; phase ^= 1; }
            }
        }
    } else {
        // ---- Phase 1: grid-cooperative flag pack (consumer warps only) ----
        {
            int gw = blockIdx.x * NCONS_W + warp;     // global consumer-warp id
            int nw_total = gridDim.x * NCONS_W;
            for (int task = gw; task < nwords4; task += nw_total) {
                int fi = task * 32 + lane;
                int4 f = (fi < nflag4) ? __ldg(&flag4[fi]) : make_int4(0, 0, 0, 0);
                unsigned int quad = ((f.x != 0) ? 1u : 0u) | ((f.y != 0) ? 2u : 0u) |
                                    ((f.z != 0) ? 4u : 0u) | ((f.w != 0) ? 8u : 0u);
                unsigned int word = quad << (4 * (lane & 7));
                word |= __shfl_xor_sync(0xFFFFFFFFu, word, 1);
                word |= __shfl_xor_sync(0xFFFFFFFFu, word, 2);
                word |= __shfl_xor_sync(0xFFFFFFFFu, word, 4);
                if ((lane & 7) == 0) {
                    int w = task * 4 + (lane >> 3);
                    if (w < MAX_WORDS) g_bits[w] = word;
                }
            }
        }
        // ---- Grid barrier: all CTAs' pack writes globally visible ----
        asm volatile("bar.sync 1, %0;" :: "n"(CONS_T) : "memory");
        if (tid == 0) {
            __threadfence();
            atomicAdd(&g_arrive, 1);
            while (*((volatile int*)&g_arrive) < (int)gridDim.x) { }
            __threadfence();
        }
        asm volatile("bar.sync 1, %0;" :: "n"(CONS_T) : "memory");

        // ---- Phase 2: stage bitmask into smem (L2 hits) ----
        for (int w = tid; w < nwords; w += CONS_T)
            s_bits[w] = g_bits[w];
        asm volatile("bar.sync 1, %0;" :: "n"(CONS_T) : "memory");

        // ---- Phase 3: pipeline consume (identical to R14) ----
        int stage = 0, phase = 0;
        int g0l = tid;
        int g1l = tid + CONS_T;
        int gs = gridDim.x;

        int t = blockIdx.x;
        float4 v_cur0 = make_float4(0.f, 0.f, 0.f, 0.f);
        float4 v_cur1 = make_float4(0.f, 0.f, 0.f, 0.f);
        if (t < ntiles) {
            int b = t * GPT;
            if (g0l < n4 - b) v_cur0 = __ldg(&vals[b + g0l]);
            if (g1l < n4 - b) v_cur1 = __ldg(&vals[b + g1l]);
        }

        for (; t < ntiles; t += gs) {
            int g0 = t * GPT;
            int cnt = min(GPT, n4 - g0);

            int tn = t + gs;
            float4 v_nx0 = make_float4(0.f, 0.f, 0.f, 0.f);
            float4 v_nx1 = make_float4(0.f, 0.f, 0.f, 0.f);
            if (tn < ntiles) {
                int bn = tn * GPT;
                if (g0l < n4 - bn) v_nx0 = __ldg(&vals[bn + g0l]);
                if (g1l < n4 - bn) v_nx1 = __ldg(&vals[bn + g1l]);
            }

            uint32_t full = mb + 16 * stage;
            mbar_wait(full, phase);              // acquire

            const unsigned char* sb = smem_raw + BUF_OFF + stage * STAGE_BYTES;
            const int4* ssrc = (const int4*)sb;
            const int4* sdst = (const int4*)(sb + BUF_BYTES);

            if (g0l < cnt)
                out[g0 + g0l] = mask_one(s_bits, ssrc[g0l], sdst[g0l], v_cur0);
            if (g1l < cnt)
                out[g0 + g1l] = mask_one(s_bits, ssrc[g1l], sdst[g1l], v_cur1);

            __syncwarp();
            if (lane == 0) mbar_arrive(full + 8);  // empty
            v_cur0 = v_nx0;
            v_cur1 = v_nx1;
            if (++stage == NSTAGES) { stage = 0; phase ^= 1; }
        }

        // ---- Reset grid-barrier counters for the next graph replay ----
        if (tid == 0) {
            int v = atomicAdd(&g_exit, 1);
            if (v == (int)gridDim.x - 1) {   // last CTA: all arrivals done
                *((volatile int*)&g_arrive) = 0;
                *((volatile int*)&g_exit)   = 0;
                __threadfence();
            }
        }
    }
}

extern "C" void kernel_launch(void* const* d_in, const int* in_sizes, int n_in,
                              void* d_out, int out_size) {
    // metadata order: edge_index [2, E] int32, values [E] f32, nodes_flag [N] int32
    const int* edge_index = (const int*)d_in[0];
    const float* values = (const float*)d_in[1];
    const int* nodes_flag = (const int*)d_in[2];
    float* out = (float*)d_out;

    int e = in_sizes[1];
    int nflags = in_sizes[2];              // 1,000,000
    int n4 = e / 4;                        // 5,000,000
    int nwords = (nflags + 31) / 32;       // 31250
    int ntiles = (n4 + GPT - 1) / GPT;
    int nflag4 = nflags / 4;               // 250,000
    int nwords4 = (nwords + 3) / 4;        // 7813 (ceil — tail covered)
    size_t smem_bytes = (size_t)BITS_OFF + (size_t)nwords * 4;  // ~223 KB

    const int* src = edge_index;
    const int* dst = edge_index + e;

    int num_sms = 148;
    cudaDeviceGetAttribute(&num_sms, cudaDevAttrMultiProcessorCount, 0);
    cudaFuncSetAttribute(node_dropout_fused,
                         cudaFuncAttributeMaxDynamicSharedMemorySize,
                         (int)smem_bytes);

    // grid == #SMs, 1 CTA/SM (smem-forced) -> all CTAs co-resident: the
    // global spin barrier cannot deadlock.
    node_dropout_fused<<<num_sms, THREADS, smem_bytes>>>(
        (const int4*)src, (const int4*)dst, (const float4*)values,
        (const int4*)nodes_flag, (float4*)out,
        n4, ntiles, nwords, nflag4, nwords4);
}

// round 16
// speedup vs baseline: 1.1096x; 1.1096x over previous
#include <cuda_runtime.h>
#include <cstdint>

// NodeDropout: out[e] = values[e] if neither endpoint is dropped, else 0.
// edge_index: int32 [2, E], values: f32 [E], nodes_flag: int32 [N]. Output: f32 [E].
//
// R16: R6's all-bulk 2-stage pipeline (best measured main) + DYNAMIC tile
// scheduling. Static round-robin makes the kernel wait on the slowest SM
// (B300 spr_max floor ~1.10 from L2-die variance); producers now fetch tiles
// from a global atomic counter and pass the tile id through smem with
// release/acquire mbarrier ordering (-1 sentinel terminates). Counters are
// reset by the last-exiting CTA so graph replays are deterministic (output is
// independent of which CTA processes which tile). Fast int4 pack kernel.

static constexpr int MAX_WORDS = 32768;
__device__ __align__(16) unsigned int g_bits[MAX_WORDS];
__device__ int g_tile;   // next tile to process (reset at end of each launch)
__device__ int g_exit;   // CTAs finished (reset by last one)

static constexpr int NCONS        = 31;            // consumer warps 0..30
static constexpr int THREADS      = 1024;          // + producer warp 31
static constexpr int CONS_T       = NCONS * 32;    // 992
static constexpr int GPT          = CONS_T;        // 992 float4-groups per tile
static constexpr int BUF_BYTES    = GPT * 16;      // 15872 per array per stage
static constexpr int STAGE_BYTES  = 3 * BUF_BYTES; // src + dst + vals = 47616
static constexpr int NSTAGES      = 2;
static constexpr int MBAR_OFF     = 0;             // full@16s, empty@16s+8
static constexpr int TILE_OFF     = 96;            // s_tile[stage] int @ 96+4s
static constexpr int BUF_OFF      = 128;
static constexpr int BITS_OFF     = BUF_OFF + NSTAGES * STAGE_BYTES; // 95360

// ---- PTX helpers ----
__device__ __forceinline__ uint32_t smem_u32(const void* p) {
    return (uint32_t)__cvta_generic_to_shared(p);
}
__device__ __forceinline__ void mbar_init(uint32_t a, uint32_t cnt) {
    asm volatile("mbarrier.init.shared.b64 [%0], %1;" :: "r"(a), "r"(cnt) : "memory");
}
__device__ __forceinline__ void mbar_expect_tx(uint32_t a, uint32_t bytes) {
    asm volatile("mbarrier.arrive.expect_tx.shared.b64 _, [%0], %1;" :: "r"(a), "r"(bytes) : "memory");
}
__device__ __forceinline__ void mbar_arrive(uint32_t a) {
    asm volatile("mbarrier.arrive.shared.b64 _, [%0];" :: "r"(a) : "memory");
}
// Acquire wait: orders BOTH bulk-completed data and the producer's generic
// STS (tile id, released by its arrive) before subsequent reads.
__device__ __forceinline__ void mbar_wait_acq(uint32_t a, uint32_t parity) {
    uint32_t done = 0;
    while (!done) {
        asm volatile(
            "{\n\t.reg .pred p;\n\t"
            "mbarrier.try_wait.parity.acquire.cta.shared::cta.b64 p, [%1], %2;\n\t"
            "selp.b32 %0, 1, 0, p;\n\t}"
            : "=r"(done) : "r"(a), "r"(parity) : "memory");
    }
}
__device__ __forceinline__ void mbar_wait(uint32_t a, uint32_t parity) {
    uint32_t done = 0;
    while (!done) {
        asm volatile(
            "{\n\t.reg .pred p;\n\t"
            "mbarrier.try_wait.parity.shared.b64 p, [%1], %2;\n\t"
            "selp.b32 %0, 1, 0, p;\n\t}"
            : "=r"(done) : "r"(a), "r"(parity) : "memory");
    }
}
__device__ __forceinline__ void bulk_g2s(uint32_t dst, const void* src,
                                         uint32_t bytes, uint32_t mbar) {
    asm volatile(
        "cp.async.bulk.shared::cluster.global.mbarrier::complete_tx::bytes "
        "[%0], [%1], %2, [%3];"
        :: "r"(dst), "l"(src), "r"(bytes), "r"(mbar) : "memory");
}

// ---- Kernel 1: pack int32 flags -> bitmask; 128 flags per warp via int4 ----
__global__ __launch_bounds__(1024)
void pack_flags_kernel(const int4* __restrict__ flag4, int nflag4, int nwords4) {
    int warp = (blockIdx.x * blockDim.x + threadIdx.x) >> 5;
    int lane = threadIdx.x & 31;
    if (warp >= nwords4) return;
    int fi = warp * 32 + lane;
    int4 f = (fi < nflag4) ? __ldg(&flag4[fi]) : make_int4(0, 0, 0, 0);
    unsigned int quad = ((f.x != 0) ? 1u : 0u) | ((f.y != 0) ? 2u : 0u) |
                        ((f.z != 0) ? 4u : 0u) | ((f.w != 0) ? 8u : 0u);
    unsigned int word = quad << (4 * (lane & 7));
    word |= __shfl_xor_sync(0xFFFFFFFFu, word, 1);
    word |= __shfl_xor_sync(0xFFFFFFFFu, word, 2);
    word |= __shfl_xor_sync(0xFFFFFFFFu, word, 4);
    if ((lane & 7) == 0) {
        int w = warp * 4 + (lane >> 3);
        if (w < MAX_WORDS) g_bits[w] = word;
    }
}

__device__ __forceinline__ float4 mask_one(const unsigned int* s_bits,
                                           int4 s, int4 d, float4 v) {
    unsigned int b0 = (s_bits[((unsigned)s.x) >> 5] >> (s.x & 31)) |
                      (s_bits[((unsigned)d.x) >> 5] >> (d.x & 31));
    unsigned int b1 = (s_bits[((unsigned)s.y) >> 5] >> (s.y & 31)) |
                      (s_bits[((unsigned)d.y) >> 5] >> (d.y & 31));
    unsigned int b2 = (s_bits[((unsigned)s.z) >> 5] >> (s.z & 31)) |
                      (s_bits[((unsigned)d.z) >> 5] >> (d.z & 31));
    unsigned int b3 = (s_bits[((unsigned)s.w) >> 5] >> (s.w & 31)) |
                      (s_bits[((unsigned)d.w) >> 5] >> (d.w & 31));
    float4 o;
    o.x = (b0 & 1u) ? 0.0f : v.x;
    o.y = (b1 & 1u) ? 0.0f : v.y;
    o.z = (b2 & 1u) ? 0.0f : v.z;
    o.w = (b3 & 1u) ? 0.0f : v.w;
    return o;
}

// ---- Kernel 2: persistent, dynamically scheduled, all-bulk pipeline ----
__global__ __launch_bounds__(THREADS, 1)
void node_dropout_kernel(const int4* __restrict__ src4,
                         const int4* __restrict__ dst4,
                         const float4* __restrict__ vals,
                         float4* __restrict__ out,
                         int n4, int ntiles, int nwords) {
    extern __shared__ __align__(16) unsigned char smem_raw[];
    unsigned int* s_bits = (unsigned int*)(smem_raw + BITS_OFF);
    int* s_tile = (int*)(smem_raw + TILE_OFF);
    uint32_t mb = smem_u32(smem_raw + MBAR_OFF);
    int tid  = threadIdx.x;
    int warp = tid >> 5;
    int lane = tid & 31;

    if (tid == 0) {
        for (int s = 0; s < NSTAGES; s++) {
            mbar_init(mb + 16 * s,     1);      // full (producer arrive/expect_tx)
            mbar_init(mb + 16 * s + 8, NCONS);  // empty
        }
    }
    __syncthreads();

    if (warp == NCONS) {
        // ---- Producer (lane 0): dynamic tile fetch ----
        if (lane == 0) {
            int stage = 0, phase = 1;   // fresh barriers pass first parity-1 waits
            for (;;) {
                int t = atomicAdd(&g_tile, 1);
                uint32_t full  = mb + 16 * stage;
                mbar_wait(full + 8, phase);        // empty
                if (t >= ntiles) {
                    s_tile[stage] = -1;            // sentinel
                    mbar_arrive(full);             // release: STS visible
                    break;
                }
                s_tile[stage] = t;
                int g0 = t * GPT;
                uint32_t bytes = (uint32_t)min(GPT, n4 - g0) * 16u;
                mbar_expect_tx(full, bytes * 3u);  // arrive (release) + tx
                uint32_t base = smem_u32(smem_raw + BUF_OFF + stage * STAGE_BYTES);
                bulk_g2s(base,                 src4 + g0, bytes, full);
                bulk_g2s(base + BUF_BYTES,     dst4 + g0, bytes, full);
                bulk_g2s(base + 2 * BUF_BYTES, vals + g0, bytes, full);
                if (++stage == NSTAGES) { stage = 0; phase ^= 1; }
            }
            // Reset scheduler state for next graph replay (last CTA out).
            __threadfence();
            int v = atomicAdd(&g_exit, 1);
            if (v == (int)gridDim.x - 1) {
                *((volatile int*)&g_tile) = 0;
                *((volatile int*)&g_exit) = 0;
                __threadfence();
            }
        }
    } else {
        // ---- Consumers: stage bitmask (int4 + tail), then pipeline loop ----
        {
            const int4* gb4 = (const int4*)g_bits;
            int4* sb4 = (int4*)s_bits;
            int nw4 = nwords >> 2;                 // 7812
            for (int w = tid; w < nw4; w += CONS_T)
                sb4[w] = __ldg(&gb4[w]);
            for (int w = (nw4 << 2) + tid; w < nwords; w += CONS_T)
                s_bits[w] = g_bits[w];
        }
        asm volatile("bar.sync 1, %0;" :: "n"(CONS_T) : "memory");

        int stage = 0, phase = 0;
        int g = tid;                               // 0..991 within tile
        for (;;) {
            uint32_t full = mb + 16 * stage;
            mbar_wait_acq(full, phase);            // acquire: data + s_tile
            int t = s_tile[stage];
            if (t < 0) break;                      // sentinel: done

            int g0 = t * GPT;
            int cnt = min(GPT, n4 - g0);
            if (g < cnt) {
                const unsigned char* sb = smem_raw + BUF_OFF + stage * STAGE_BYTES;
                int4   s = ((const int4*)  (sb))[g];
                int4   d = ((const int4*)  (sb + BUF_BYTES))[g];
                float4 v = ((const float4*)(sb + 2 * BUF_BYTES))[g];
                out[g0 + g] = mask_one(s_bits, s, d, v);
            }
            __syncwarp();
            if (lane == 0) mbar_arrive(full + 8);  // empty
            if (++stage == NSTAGES) { stage = 0; phase ^= 1; }
        }
    }
}

extern "C" void kernel_launch(void* const* d_in, const int* in_sizes, int n_in,
                              void* d_out, int out_size) {
    // metadata order: edge_index [2, E] int32, values [E] f32, nodes_flag [N] int32
    const int* edge_index = (const int*)d_in[0];
    const float* values = (const float*)d_in[1];
    const int* nodes_flag = (const int*)d_in[2];
    float* out = (float*)d_out;

    int e = in_sizes[1];
    int nflags = in_sizes[2];              // 1,000,000
    int n4 = e / 4;                        // 5,000,000
    int nwords = (nflags + 31) / 32;       // 31250
    int ntiles = (n4 + GPT - 1) / GPT;     // 5041
    size_t smem_bytes = (size_t)BITS_OFF + (size_t)nwords * 4;  // 220360

    const int* src = edge_index;
    const int* dst = edge_index + e;

    int nflag4 = nflags / 4;
    int nwords4 = (nwords + 3) / 4;        // ceil — tail words covered
    int pack_blocks = (nwords4 * 32 + 1023) / 1024;
    pack_flags_kernel<<<pack_blocks, 1024>>>((const int4*)nodes_flag, nflag4, nwords4);

    int num_sms = 148;
    cudaDeviceGetAttribute(&num_sms, cudaDevAttrMultiProcessorCount, 0);
    cudaFuncSetAttribute(node_dropout_kernel,
                         cudaFuncAttributeMaxDynamicSharedMemorySize,
                         (int)smem_bytes);

    // grid == #SMs, 1 CTA/SM (smem-forced): all CTAs co-resident.
    node_dropout_kernel<<<num_sms, THREADS, smem_bytes>>>(
        (const int4*)src, (const int4*)dst, (const float4*)values,
        (float4*)out, n4, ntiles, nwords);
}

// round 17
// speedup vs baseline: 1.1457x; 1.0326x over previous
#include <cuda_runtime.h>
#include <cstdint>

// NodeDropout: out[e] = values[e] if neither endpoint is dropped, else 0.
// edge_index: int32 [2, E], values: f32 [E], nodes_flag: int32 [N]. Output: f32 [E].
//
// R17 = R16 (all-bulk pipeline + dynamic tile scheduling via global atomic,
// tile id passed through smem with release/acquire mbarrier ordering) with
// NSTAGES 2 -> 3 (GPT 992 -> 704, 22 consumer warps) so the producer holds
// three tiles in flight: R16 showed ~20% of main-loop time is residual
// pipeline bubbles that a 2-deep ring can't absorb.

static constexpr int MAX_WORDS = 32768;
__device__ __align__(16) unsigned int g_bits[MAX_WORDS];
__device__ int g_tile;   // next tile (reset by last exiting CTA each launch)
__device__ int g_exit;   // exit count for reset handshake

static constexpr int NCONS        = 22;            // consumer warps 0..21
static constexpr int THREADS      = (NCONS + 1) * 32;  // 736 (+ producer warp)
static constexpr int CONS_T       = NCONS * 32;    // 704
static constexpr int GPT          = CONS_T;        // 704 float4-groups per tile
static constexpr int BUF_BYTES    = GPT * 16;      // 11264 per array per stage
static constexpr int STAGE_BYTES  = 3 * BUF_BYTES; // src + dst + vals = 33792
static constexpr int NSTAGES      = 3;
static constexpr int MBAR_OFF     = 0;             // full@16s, empty@16s+8
static constexpr int TILE_OFF     = 96;            // s_tile[stage] int @ 96+4s
static constexpr int BUF_OFF      = 128;
static constexpr int BITS_OFF     = BUF_OFF + NSTAGES * STAGE_BYTES; // 101504

// ---- PTX helpers ----
__device__ __forceinline__ uint32_t smem_u32(const void* p) {
    return (uint32_t)__cvta_generic_to_shared(p);
}
__device__ __forceinline__ void mbar_init(uint32_t a, uint32_t cnt) {
    asm volatile("mbarrier.init.shared.b64 [%0], %1;" :: "r"(a), "r"(cnt) : "memory");
}
__device__ __forceinline__ void mbar_expect_tx(uint32_t a, uint32_t bytes) {
    asm volatile("mbarrier.arrive.expect_tx.shared.b64 _, [%0], %1;" :: "r"(a), "r"(bytes) : "memory");
}
__device__ __forceinline__ void mbar_arrive(uint32_t a) {
    asm volatile("mbarrier.arrive.shared.b64 _, [%0];" :: "r"(a) : "memory");
}
// Acquire wait: orders bulk-completed data AND the producer's generic STS
// (tile id, released by its arrive) before subsequent reads.
__device__ __forceinline__ void mbar_wait_acq(uint32_t a, uint32_t parity) {
    uint32_t done = 0;
    while (!done) {
        asm volatile(
            "{\n\t.reg .pred p;\n\t"
            "mbarrier.try_wait.parity.acquire.cta.shared::cta.b64 p, [%1], %2;\n\t"
            "selp.b32 %0, 1, 0, p;\n\t}"
            : "=r"(done) : "r"(a), "r"(parity) : "memory");
    }
}
__device__ __forceinline__ void mbar_wait(uint32_t a, uint32_t parity) {
    uint32_t done = 0;
    while (!done) {
        asm volatile(
            "{\n\t.reg .pred p;\n\t"
            "mbarrier.try_wait.parity.shared.b64 p, [%1], %2;\n\t"
            "selp.b32 %0, 1, 0, p;\n\t}"
            : "=r"(done) : "r"(a), "r"(parity) : "memory");
    }
}
__device__ __forceinline__ void bulk_g2s(uint32_t dst, const void* src,
                                         uint32_t bytes, uint32_t mbar) {
    asm volatile(
        "cp.async.bulk.shared::cluster.global.mbarrier::complete_tx::bytes "
        "[%0], [%1], %2, [%3];"
        :: "r"(dst), "l"(src), "r"(bytes), "r"(mbar) : "memory");
}

// ---- Kernel 1: pack int32 flags -> bitmask; 128 flags per warp via int4 ----
__global__ __launch_bounds__(1024)
void pack_flags_kernel(const int4* __restrict__ flag4, int nflag4, int nwords4) {
    int warp = (blockIdx.x * blockDim.x + threadIdx.x) >> 5;
    int lane = threadIdx.x & 31;
    if (warp >= nwords4) return;
    int fi = warp * 32 + lane;
    int4 f = (fi < nflag4) ? __ldg(&flag4[fi]) : make_int4(0, 0, 0, 0);
    unsigned int quad = ((f.x != 0) ? 1u : 0u) | ((f.y != 0) ? 2u : 0u) |
                        ((f.z != 0) ? 4u : 0u) | ((f.w != 0) ? 8u : 0u);
    unsigned int word = quad << (4 * (lane & 7));
    word |= __shfl_xor_sync(0xFFFFFFFFu, word, 1);
    word |= __shfl_xor_sync(0xFFFFFFFFu, word, 2);
    word |= __shfl_xor_sync(0xFFFFFFFFu, word, 4);
    if ((lane & 7) == 0) {
        int w = warp * 4 + (lane >> 3);
        if (w < MAX_WORDS) g_bits[w] = word;
    }
}

__device__ __forceinline__ float4 mask_one(const unsigned int* s_bits,
                                           int4 s, int4 d, float4 v) {
    unsigned int b0 = (s_bits[((unsigned)s.x) >> 5] >> (s.x & 31)) |
                      (s_bits[((unsigned)d.x) >> 5] >> (d.x & 31));
    unsigned int b1 = (s_bits[((unsigned)s.y) >> 5] >> (s.y & 31)) |
                      (s_bits[((unsigned)d.y) >> 5] >> (d.y & 31));
    unsigned int b2 = (s_bits[((unsigned)s.z) >> 5] >> (s.z & 31)) |
                      (s_bits[((unsigned)d.z) >> 5] >> (d.z & 31));
    unsigned int b3 = (s_bits[((unsigned)s.w) >> 5] >> (s.w & 31)) |
                      (s_bits[((unsigned)d.w) >> 5] >> (d.w & 31));
    float4 o;
    o.x = (b0 & 1u) ? 0.0f : v.x;
    o.y = (b1 & 1u) ? 0.0f : v.y;
    o.z = (b2 & 1u) ? 0.0f : v.z;
    o.w = (b3 & 1u) ? 0.0f : v.w;
    return o;
}

// ---- Kernel 2: persistent, dynamically scheduled, all-bulk pipeline ----
__global__ __launch_bounds__(THREADS, 1)
void node_dropout_kernel(const int4* __restrict__ src4,
                         const int4* __restrict__ dst4,
                         const float4* __restrict__ vals,
                         float4* __restrict__ out,
                         int n4, int ntiles, int nwords) {
    extern __shared__ __align__(16) unsigned char smem_raw[];
    unsigned int* s_bits = (unsigned int*)(smem_raw + BITS_OFF);
    int* s_tile = (int*)(smem_raw + TILE_OFF);
    uint32_t mb = smem_u32(smem_raw + MBAR_OFF);
    int tid  = threadIdx.x;
    int warp = tid >> 5;
    int lane = tid & 31;

    if (tid == 0) {
        for (int s = 0; s < NSTAGES; s++) {
            mbar_init(mb + 16 * s,     1);      // full (producer arrive/expect_tx)
            mbar_init(mb + 16 * s + 8, NCONS);  // empty
        }
    }
    __syncthreads();

    if (warp == NCONS) {
        // ---- Producer (lane 0): dynamic tile fetch ----
        if (lane == 0) {
            int stage = 0, phase = 1;   // fresh barriers pass first parity-1 waits
            for (;;) {
                int t = atomicAdd(&g_tile, 1);     // latency overlaps empty wait
                uint32_t full  = mb + 16 * stage;
                mbar_wait(full + 8, phase);        // empty
                if (t >= ntiles) {
                    s_tile[stage] = -1;            // sentinel
                    mbar_arrive(full);             // release: STS visible
                    break;
                }
                s_tile[stage] = t;
                int g0 = t * GPT;
                uint32_t bytes = (uint32_t)min(GPT, n4 - g0) * 16u;
                mbar_expect_tx(full, bytes * 3u);  // arrive (release) + tx
                uint32_t base = smem_u32(smem_raw + BUF_OFF + stage * STAGE_BYTES);
                bulk_g2s(base,                 src4 + g0, bytes, full);
                bulk_g2s(base + BUF_BYTES,     dst4 + g0, bytes, full);
                bulk_g2s(base + 2 * BUF_BYTES, vals + g0, bytes, full);
                if (++stage == NSTAGES) { stage = 0; phase ^= 1; }
            }
            // Reset scheduler state for the next graph replay (last CTA out).
            __threadfence();
            int v = atomicAdd(&g_exit, 1);
            if (v == (int)gridDim.x - 1) {
                *((volatile int*)&g_tile) = 0;
                *((volatile int*)&g_exit) = 0;
                __threadfence();
            }
        }
    } else {
        // ---- Consumers: stage bitmask (int4 + tail), then pipeline loop ----
        {
            const int4* gb4 = (const int4*)g_bits;
            int4* sb4 = (int4*)s_bits;
            int nw4 = nwords >> 2;                 // 7812
            for (int w = tid; w < nw4; w += CONS_T)
                sb4[w] = __ldg(&gb4[w]);
            for (int w = (nw4 << 2) + tid; w < nwords; w += CONS_T)
                s_bits[w] = g_bits[w];
        }
        asm volatile("bar.sync 1, %0;" :: "n"(CONS_T) : "memory");

        int stage = 0, phase = 0;
        int g = tid;                               // 0..GPT-1 within tile
        for (;;) {
            uint32_t full = mb + 16 * stage;
            mbar_wait_acq(full, phase);            // acquire: data + s_tile
            int t = s_tile[stage];
            if (t < 0) break;                      // sentinel: done

            int g0 = t * GPT;
            int cnt = min(GPT, n4 - g0);
            if (g < cnt) {
                const unsigned char* sb = smem_raw + BUF_OFF + stage * STAGE_BYTES;
                int4   s = ((const int4*)  (sb))[g];
                int4   d = ((const int4*)  (sb + BUF_BYTES))[g];
                float4 v = ((const float4*)(sb + 2 * BUF_BYTES))[g];
                out[g0 + g] = mask_one(s_bits, s, d, v);
            }
            __syncwarp();
            if (lane == 0) mbar_arrive(full + 8);  // empty
            if (++stage == NSTAGES) { stage = 0; phase ^= 1; }
        }
    }
}

extern "C" void kernel_launch(void* const* d_in, const int* in_sizes, int n_in,
                              void* d_out, int out_size) {
    // metadata order: edge_index [2, E] int32, values [E] f32, nodes_flag [N] int32
    const int* edge_index = (const int*)d_in[0];
    const float* values = (const float*)d_in[1];
    const int* nodes_flag = (const int*)d_in[2];
    float* out = (float*)d_out;

    int e = in_sizes[1];
    int nflags = in_sizes[2];              // 1,000,000
    int n4 = e / 4;                        // 5,000,000
    int nwords = (nflags + 31) / 32;       // 31250
    int ntiles = (n4 + GPT - 1) / GPT;     // 7103
    size_t smem_bytes = (size_t)BITS_OFF + (size_t)nwords * 4;  // 226504

    const int* src = edge_index;
    const int* dst = edge_index + e;

    int nflag4 = nflags / 4;
    int nwords4 = (nwords + 3) / 4;        // ceil — tail words covered
    int pack_blocks = (nwords4 * 32 + 1023) / 1024;
    pack_flags_kernel<<<pack_blocks, 1024>>>((const int4*)nodes_flag, nflag4, nwords4);

    int num_sms = 148;
    cudaDeviceGetAttribute(&num_sms, cudaDevAttrMultiProcessorCount, 0);
    cudaFuncSetAttribute(node_dropout_kernel,
                         cudaFuncAttributeMaxDynamicSharedMemorySize,
                         (int)smem_bytes);

    // grid == #SMs, 1 CTA/SM (smem-forced): all CTAs co-resident.
    node_dropout_kernel<<<num_sms, THREADS, smem_bytes>>>(
        (const int4*)src, (const int4*)dst, (const float4*)values,
        (float4*)out, n4, ntiles, nwords);
}